// round 1
// baseline (speedup 1.0000x reference)
#include <cuda_runtime.h>
#include <math.h>

// Problem dims (fixed by the dataset)
#define N_TOK 65536
#define DIM   256
#define NEXP  4
#define HID   512
#define EMBD  512

// ---------------- scratch (device globals; no runtime allocation) -------------
__device__ float g_gates[(size_t)N_TOK * NEXP];          // 1 MB, dense gate matrix
__device__ float g_h[(size_t)N_TOK * HID];                // 128 MB, per-expert hidden
__device__ float g_y[(size_t)N_TOK * DIM];                // 64 MB, combined expert out

// ---------------- packed f32x2 helpers (FFMA2 path, 2x FFMA rate) --------------
__device__ __forceinline__ void fma2(unsigned long long& c, unsigned long long a,
                                     unsigned long long b) {
    asm("fma.rn.f32x2 %0, %1, %2, %0;" : "+l"(c) : "l"(a), "l"(b));
}
__device__ __forceinline__ unsigned long long pack2(float x) {
    unsigned long long r;
    asm("mov.b64 %0, {%1, %1};" : "=l"(r) : "f"(x));
    return r;
}
__device__ __forceinline__ float2 unpack2(unsigned long long v) {
    float2 r;
    asm("mov.b64 {%0, %1}, %2;" : "=f"(r.x), "=f"(r.y) : "l"(v));
    return r;
}

__device__ __forceinline__ float gelu_exact(float x) {
    // jax.nn.gelu(approximate=False) == x * Phi(x)
    return x * normcdff(x);
}

// ---------------- gating: logits -> top-2 -> softmax -> dense gates ------------
__global__ void gate_kernel(const float* __restrict__ x, const float* __restrict__ wg) {
    __shared__ float sw[DIM * NEXP];
    int tid = threadIdx.x;
    for (int i = tid; i < DIM * NEXP; i += blockDim.x) sw[i] = wg[i];
    __syncthreads();

    int warp = tid >> 5, lane = tid & 31;
    int token = blockIdx.x * (blockDim.x >> 5) + warp;
    const float* xr = x + (size_t)token * DIM;

    float s0 = 0.f, s1 = 0.f, s2 = 0.f, s3 = 0.f;
    #pragma unroll
    for (int d = lane; d < DIM; d += 32) {
        float xv = xr[d];
        s0 += xv * sw[d * NEXP + 0];
        s1 += xv * sw[d * NEXP + 1];
        s2 += xv * sw[d * NEXP + 2];
        s3 += xv * sw[d * NEXP + 3];
    }
    #pragma unroll
    for (int o = 16; o > 0; o >>= 1) {
        s0 += __shfl_down_sync(0xffffffffu, s0, o);
        s1 += __shfl_down_sync(0xffffffffu, s1, o);
        s2 += __shfl_down_sync(0xffffffffu, s2, o);
        s3 += __shfl_down_sync(0xffffffffu, s3, o);
    }
    if (lane == 0) {
        float l[NEXP] = {s0, s1, s2, s3};
        int i1 = 0;
        #pragma unroll
        for (int e = 1; e < NEXP; e++) if (l[e] > l[i1]) i1 = e;   // stable: first max
        int i2 = -1;
        #pragma unroll
        for (int e = 0; e < NEXP; e++) {
            if (e == i1) continue;
            if (i2 < 0 || l[e] > l[i2]) i2 = e;                    // stable second
        }
        float t  = expf(l[i2] - l[i1]);   // <= 1, numerically safe
        float inv = 1.0f / (1.0f + t);
        float out[NEXP] = {0.f, 0.f, 0.f, 0.f};
        out[i1] = inv;
        out[i2] = t * inv;
        *(float4*)(g_gates + (size_t)token * NEXP) =
            make_float4(out[0], out[1], out[2], out[3]);
    }
}

// ---------------- tiled SGEMM with f32x2 inner loop ----------------------------
// C[M,Ncols] (+)= epilogue( A[M,KDIM] @ B[KDIM,Ncols] )
// MODE 0: C = gelu(AB)
// MODE 1: C (+)= gate[row,expert] * AB      (accumulate flag selects write/add)
// MODE 2: C = AB + bias[col]
#define BM 128
#define BN 128
#define BKT 32
#define AS_STRIDE 132   // +4 pad kills 8-way STS bank conflicts on the transpose

template <int KDIM, int MODE>
__global__ __launch_bounds__(256, 2) void gemm_kernel(
    const float* __restrict__ A, const float* __restrict__ B,
    float* __restrict__ C, int Ncols,
    const float* __restrict__ aux, int expert, int accumulate)
{
    __shared__ float As[BKT * AS_STRIDE];
    __shared__ float Bs[BKT * BN];

    int tid = threadIdx.x;
    int tx = tid & 15;        // 16 cols of threads -> 8 output cols each
    int ty = tid >> 4;        // 16 rows of threads -> 8 output rows each
    int m0 = blockIdx.y * BM;
    int n0 = blockIdx.x * BN;

    unsigned long long acc[8][4];
    #pragma unroll
    for (int i = 0; i < 8; i++)
        #pragma unroll
        for (int j = 0; j < 4; j++) acc[i][j] = 0ULL;   // {0.f,0.f}

    const float* Ab = A + (size_t)m0 * KDIM;
    const float* Bb = B + n0;

    for (int k0 = 0; k0 < KDIM; k0 += BKT) {
        // --- stage A tile transposed: As[k][m], 1024 float4 loads total
        #pragma unroll
        for (int i = 0; i < 4; i++) {
            int f = tid + i * 256;
            int row = f >> 3;      // 8 float4 per A row (BKT=32 floats)
            int cg  = f & 7;
            float4 v = *(const float4*)(Ab + (size_t)row * KDIM + k0 + cg * 4);
            As[(cg * 4 + 0) * AS_STRIDE + row] = v.x;
            As[(cg * 4 + 1) * AS_STRIDE + row] = v.y;
            As[(cg * 4 + 2) * AS_STRIDE + row] = v.z;
            As[(cg * 4 + 3) * AS_STRIDE + row] = v.w;
        }
        // --- stage B tile natural: Bs[k][n]
        #pragma unroll
        for (int i = 0; i < 4; i++) {
            int f = tid + i * 256;
            int row = f >> 5;      // 32 float4 per B row (BN=128 floats)
            int cg  = f & 31;
            *(float4*)(Bs + row * BN + cg * 4) =
                *(const float4*)(Bb + (size_t)(k0 + row) * Ncols + cg * 4);
        }
        __syncthreads();

        #pragma unroll
        for (int kk = 0; kk < BKT; kk++) {
            const float* arow = As + kk * AS_STRIDE + ty * 8;
            float4 a0 = *(const float4*)(arow);
            float4 a1 = *(const float4*)(arow + 4);
            unsigned long long ap[8] = {
                pack2(a0.x), pack2(a0.y), pack2(a0.z), pack2(a0.w),
                pack2(a1.x), pack2(a1.y), pack2(a1.z), pack2(a1.w)};
            const unsigned long long* brow =
                (const unsigned long long*)(Bs + kk * BN) + tx * 4;
            unsigned long long b0 = brow[0], b1 = brow[1], b2 = brow[2], b3 = brow[3];
            #pragma unroll
            for (int i = 0; i < 8; i++) {
                fma2(acc[i][0], ap[i], b0);
                fma2(acc[i][1], ap[i], b1);
                fma2(acc[i][2], ap[i], b2);
                fma2(acc[i][3], ap[i], b3);
            }
        }
        __syncthreads();
    }

    // ---------------- epilogue ----------------
    #pragma unroll
    for (int i = 0; i < 8; i++) {
        int grow = m0 + ty * 8 + i;
        float* Crow = C + (size_t)grow * Ncols + n0 + tx * 8;
        float c[8];
        #pragma unroll
        for (int j = 0; j < 4; j++) {
            float2 v = unpack2(acc[i][j]);
            c[2 * j] = v.x;
            c[2 * j + 1] = v.y;
        }
        if (MODE == 0) {
            #pragma unroll
            for (int j = 0; j < 8; j++) c[j] = gelu_exact(c[j]);
            *(float4*)(Crow)     = make_float4(c[0], c[1], c[2], c[3]);
            *(float4*)(Crow + 4) = make_float4(c[4], c[5], c[6], c[7]);
        } else if (MODE == 1) {
            float g = aux[(size_t)grow * NEXP + expert];
            if (accumulate) {
                if (g != 0.0f) {
                    float4 o0 = *(const float4*)(Crow);
                    float4 o1 = *(const float4*)(Crow + 4);
                    *(float4*)(Crow) = make_float4(o0.x + g * c[0], o0.y + g * c[1],
                                                   o0.z + g * c[2], o0.w + g * c[3]);
                    *(float4*)(Crow + 4) = make_float4(o1.x + g * c[4], o1.y + g * c[5],
                                                       o1.z + g * c[6], o1.w + g * c[7]);
                }
            } else {
                *(float4*)(Crow)     = make_float4(g * c[0], g * c[1], g * c[2], g * c[3]);
                *(float4*)(Crow + 4) = make_float4(g * c[4], g * c[5], g * c[6], g * c[7]);
            }
        } else {  // MODE 2: + bias
            const float* bb = aux + n0 + tx * 8;
            *(float4*)(Crow)     = make_float4(c[0] + bb[0], c[1] + bb[1],
                                               c[2] + bb[2], c[3] + bb[3]);
            *(float4*)(Crow + 4) = make_float4(c[4] + bb[4], c[5] + bb[5],
                                               c[6] + bb[6], c[7] + bb[7]);
        }
    }
}

// ---------------- launch --------------------------------------------------------
extern "C" void kernel_launch(void* const* d_in, const int* in_sizes, int n_in,
                              void* d_out, int out_size) {
    const float* x      = (const float*)d_in[0];   // [N, D]
    const float* w_gate = (const float*)d_in[1];   // [D, E]
    const float* w1     = (const float*)d_in[2];   // [E, D, H]
    const float* w2     = (const float*)d_in[3];   // [E, H, D]
    const float* w_proj = (const float*)d_in[4];   // [D, EMB]
    const float* b_proj = (const float*)d_in[5];   // [EMB]
    float* out = (float*)d_out;                    // [N, EMB]

    float *gates_p, *h_p, *y_p;
    cudaGetSymbolAddress((void**)&gates_p, g_gates);
    cudaGetSymbolAddress((void**)&h_p, g_h);
    cudaGetSymbolAddress((void**)&y_p, g_y);

    // 1) gating
    gate_kernel<<<N_TOK / 8, 256>>>(x, w_gate);

    // 2) experts: h = gelu(x @ w1[e]);  y (+)= gate[:,e] * (h @ w2[e])
    for (int e = 0; e < NEXP; e++) {
        gemm_kernel<DIM, 0><<<dim3(HID / BN, N_TOK / BM), 256>>>(
            x, w1 + (size_t)e * DIM * HID, h_p, HID, nullptr, 0, 0);
        gemm_kernel<HID, 1><<<dim3(DIM / BN, N_TOK / BM), 256>>>(
            h_p, w2 + (size_t)e * HID * DIM, y_p, DIM, gates_p, e, e > 0 ? 1 : 0);
    }

    // 3) output projection: out = y @ w_proj + b
    gemm_kernel<DIM, 2><<<dim3(EMBD / BN, N_TOK / BM), 256>>>(
        y_p, w_proj, out, EMBD, b_proj, 0, 0);
}

// round 3
// speedup vs baseline: 2.3146x; 2.3146x over previous
#include <cuda_runtime.h>
#include <math.h>
#include <cstdint>

// Problem dims
#define N_TOK 65536
#define DIM   256
#define NEXP  4
#define HID   512
#define EMBD  512
#define KCAT  (NEXP * HID)   // 2048

// ---------------- scratch (device globals) -------------------------------------
__device__ float g_gates[(size_t)N_TOK * NEXP];     // 1 MB
__device__ float g_xt[(size_t)N_TOK * DIM];         // 64 MB  (tf32-rounded x)
__device__ float g_h[(size_t)N_TOK * KCAT];         // 512 MB (gated gelu hidden)
__device__ float g_y[(size_t)N_TOK * DIM];          // 64 MB
__device__ float g_w1t[NEXP * HID * DIM];           // [e][H][D]
__device__ float g_w2t[DIM * KCAT];                 // [D][E*H]
__device__ float g_wpt[EMBD * DIM];                 // [EMB][D]

// ---------------- helpers -------------------------------------------------------
__device__ __forceinline__ uint32_t smem_to_u32(const void* p) {
    uint32_t a;
    asm("{ .reg .u64 t; cvta.to.shared.u64 t, %1; cvt.u32.u64 %0, t; }" : "=r"(a) : "l"(p));
    return a;
}
__device__ __forceinline__ uint32_t rna_tf32(float f) {
    uint32_t r;
    asm("cvt.rna.tf32.f32 %0, %1;" : "=r"(r) : "f"(f));
    return r;
}
__device__ __forceinline__ void cp_async16(uint32_t dst, const void* src) {
    asm volatile("cp.async.cg.shared.global [%0], [%1], 16;"
                 :: "r"(dst), "l"(src) : "memory");
}
__device__ __forceinline__ void mma_tf32(float c[4], uint32_t a0, uint32_t a1,
                                         uint32_t a2, uint32_t a3,
                                         uint32_t b0, uint32_t b1) {
    asm volatile(
        "mma.sync.aligned.m16n8k8.row.col.f32.tf32.tf32.f32 "
        "{%0,%1,%2,%3}, {%4,%5,%6,%7}, {%8,%9}, {%0,%1,%2,%3};"
        : "+f"(c[0]), "+f"(c[1]), "+f"(c[2]), "+f"(c[3])
        : "r"(a0), "r"(a1), "r"(a2), "r"(a3), "r"(b0), "r"(b1));
}

// ---------------- gating --------------------------------------------------------
__global__ void gate_kernel(const float* __restrict__ x, const float* __restrict__ wg) {
    __shared__ float sw[DIM * NEXP];
    int tid = threadIdx.x;
    for (int i = tid; i < DIM * NEXP; i += blockDim.x) sw[i] = wg[i];
    __syncthreads();
    int warp = tid >> 5, lane = tid & 31;
    int token = blockIdx.x * (blockDim.x >> 5) + warp;
    const float* xr = x + (size_t)token * DIM;
    float s0 = 0.f, s1 = 0.f, s2 = 0.f, s3 = 0.f;
    #pragma unroll
    for (int d = lane; d < DIM; d += 32) {
        float xv = xr[d];
        s0 += xv * sw[d * NEXP + 0];
        s1 += xv * sw[d * NEXP + 1];
        s2 += xv * sw[d * NEXP + 2];
        s3 += xv * sw[d * NEXP + 3];
    }
    #pragma unroll
    for (int o = 16; o > 0; o >>= 1) {
        s0 += __shfl_down_sync(0xffffffffu, s0, o);
        s1 += __shfl_down_sync(0xffffffffu, s1, o);
        s2 += __shfl_down_sync(0xffffffffu, s2, o);
        s3 += __shfl_down_sync(0xffffffffu, s3, o);
    }
    if (lane == 0) {
        float l[NEXP] = {s0, s1, s2, s3};
        int i1 = 0;
        #pragma unroll
        for (int e = 1; e < NEXP; e++) if (l[e] > l[i1]) i1 = e;
        int i2 = -1;
        #pragma unroll
        for (int e = 0; e < NEXP; e++) {
            if (e == i1) continue;
            if (i2 < 0 || l[e] > l[i2]) i2 = e;
        }
        float t = expf(l[i2] - l[i1]);
        float inv = 1.0f / (1.0f + t);
        float out[NEXP] = {0.f, 0.f, 0.f, 0.f};
        out[i1] = inv;
        out[i2] = t * inv;
        *(float4*)(g_gates + (size_t)token * NEXP) = make_float4(out[0], out[1], out[2], out[3]);
    }
}

// ---------------- prep: rna-round x ----------------------------------------------
__global__ void round_x_kernel(const float4* __restrict__ in, float4* __restrict__ out) {
    size_t i = (size_t)blockIdx.x * blockDim.x + threadIdx.x;
    float4 v = in[i];
    uint4 r;
    r.x = rna_tf32(v.x); r.y = rna_tf32(v.y); r.z = rna_tf32(v.z); r.w = rna_tf32(v.w);
    *(uint4*)(out + i) = r;
}

// ---------------- prep: transpose + rna-round weights -----------------------------
__global__ void transpose_rna_kernel(const float* __restrict__ in, float* __restrict__ out,
                                     int K, int N) {
    __shared__ float t[32][33];
    int b = blockIdx.z;
    in  += (size_t)b * K * N;
    out += (size_t)b * K * N;
    int n0 = blockIdx.x * 32, k0 = blockIdx.y * 32;
    int tx = threadIdx.x, ty = threadIdx.y;  // 32 x 8
    #pragma unroll
    for (int j = 0; j < 32; j += 8)
        t[ty + j][tx] = in[(size_t)(k0 + ty + j) * N + n0 + tx];
    __syncthreads();
    #pragma unroll
    for (int j = 0; j < 32; j += 8)
        out[(size_t)(n0 + ty + j) * K + k0 + tx] = __uint_as_float(rna_tf32(t[tx][ty + j]));
}

// ---------------- mma.sync tf32 GEMM ----------------------------------------------
// C[M, ldC] (cols n0 + e*c_zmul ...) = epi( A[M,KDIM] @ Bt[N,KDIM]^T )
// MODE 0: rna(gate[m,e] * gelu(v)); MODE 1: rna(v); MODE 2: v + bias[col]
#define BM 128
#define BN 128
#define BK 32
#define SA 36                     // floats per smem row (bank-conflict-free)
#define TILE_F (128 * SA)         // 4608 floats per tile
#define STAGE_F (2 * TILE_F)      // A + B
#define SMEM_BYTES (2 * STAGE_F * 4)   // double buffered = 73728 B

template <int KDIM, int MODE>
__global__ void __launch_bounds__(256, 2) gemm_mma(
    const float* __restrict__ A,
    const float* __restrict__ Bt,
    float* __restrict__ C, int ldC,
    const float* __restrict__ aux,
    int bt_zstride, int c_zmul)
{
    extern __shared__ float sm[];
    const uint32_t smem_base = smem_to_u32(sm);

    const int tid = threadIdx.x;
    const int wid = tid >> 5, lane = tid & 31;
    const int gr = lane >> 2, gc = lane & 3;
    const int warpM = wid >> 2, warpN = wid & 3;
    const int m0 = blockIdx.y * BM, n0 = blockIdx.x * BN, e = blockIdx.z;
    const int NCH = KDIM / BK;

    const float* Ag = A + (size_t)m0 * KDIM;
    const float* Bg = Bt + (size_t)e * bt_zstride + (size_t)n0 * KDIM;

    float acc[4][4][4];
    #pragma unroll
    for (int mi = 0; mi < 4; mi++)
        #pragma unroll
        for (int ni = 0; ni < 4; ni++)
            #pragma unroll
            for (int j = 0; j < 4; j++) acc[mi][ni][j] = 0.f;

    // thread's staging slots (fixed across chunks)
    const int f_row = tid >> 1;                // 0..127 (two threads per row)
    const int f_cg0 = (tid & 1) * 4;           // 0 or 4 -> covers cg 0..3 / 4..7

    // per-chunk staging: 2048 x 16B; thread does 8: 4 for A row f_row, 4 for B row f_row
    auto issue_stage = [&](int c) {
        const int s = c & 1;
        const uint32_t sb = smem_base + (uint32_t)s * (STAGE_F * 4);
        const int k0 = c * BK;
        const float* srcA = Ag + (size_t)f_row * KDIM + k0 + f_cg0 * 4;
        const float* srcB = Bg + (size_t)f_row * KDIM + k0 + f_cg0 * 4;
        const uint32_t dA = sb + f_row * (SA * 4) + f_cg0 * 16;
        const uint32_t dB = dA + TILE_F * 4;
        #pragma unroll
        for (int i = 0; i < 4; i++) cp_async16(dA + i * 16, srcA + i * 4);
        #pragma unroll
        for (int i = 0; i < 4; i++) cp_async16(dB + i * 16, srcB + i * 4);
        asm volatile("cp.async.commit_group;" ::: "memory");
    };

    issue_stage(0);

    for (int c = 0; c < NCH; c++) {
        if (c + 1 < NCH) {
            issue_stage(c + 1);
            asm volatile("cp.async.wait_group 1;" ::: "memory");
        } else {
            asm volatile("cp.async.wait_group 0;" ::: "memory");
        }
        __syncthreads();

        const float* As = sm + (c & 1) * STAGE_F;
        const float* Bs = As + TILE_F;
        const float* ap = As + (warpM * 64 + gr) * SA + gc;
        const float* bp = Bs + (warpN * 32 + gr) * SA + gc;

        #pragma unroll
        for (int kk = 0; kk < 4; kk++) {
            const float* apk = ap + kk * 8;
            const float* bpk = bp + kk * 8;
            uint32_t bf[4][2];
            #pragma unroll
            for (int ni = 0; ni < 4; ni++) {
                bf[ni][0] = __float_as_uint(bpk[ni * 8 * SA]);
                bf[ni][1] = __float_as_uint(bpk[ni * 8 * SA + 4]);
            }
            #pragma unroll
            for (int mi = 0; mi < 4; mi++) {
                uint32_t a0 = __float_as_uint(apk[mi * 16 * SA]);
                uint32_t a1 = __float_as_uint(apk[mi * 16 * SA + 8 * SA]);
                uint32_t a2 = __float_as_uint(apk[mi * 16 * SA + 4]);
                uint32_t a3 = __float_as_uint(apk[mi * 16 * SA + 8 * SA + 4]);
                #pragma unroll
                for (int ni = 0; ni < 4; ni++)
                    mma_tf32(acc[mi][ni], a0, a1, a2, a3, bf[ni][0], bf[ni][1]);
            }
        }
        __syncthreads();
    }

    // ---------------- epilogue ----------------
    const int cofs = n0 + e * c_zmul;
    #pragma unroll
    for (int mi = 0; mi < 4; mi++) {
        const int r0 = m0 + warpM * 64 + mi * 16 + gr;
        float g0 = 0.f, g1 = 0.f;
        if (MODE == 0) {
            g0 = g_gates[(size_t)r0 * NEXP + e];
            g1 = g_gates[(size_t)(r0 + 8) * NEXP + e];
        }
        #pragma unroll
        for (int ni = 0; ni < 4; ni++) {
            const int col = cofs + warpN * 32 + ni * 8 + gc * 2;
            float c0 = acc[mi][ni][0], c1 = acc[mi][ni][1];
            float c2 = acc[mi][ni][2], c3 = acc[mi][ni][3];
            if (MODE == 0) {
                c0 = __uint_as_float(rna_tf32(g0 * (c0 * normcdff(c0))));
                c1 = __uint_as_float(rna_tf32(g0 * (c1 * normcdff(c1))));
                c2 = __uint_as_float(rna_tf32(g1 * (c2 * normcdff(c2))));
                c3 = __uint_as_float(rna_tf32(g1 * (c3 * normcdff(c3))));
            } else if (MODE == 1) {
                c0 = __uint_as_float(rna_tf32(c0));
                c1 = __uint_as_float(rna_tf32(c1));
                c2 = __uint_as_float(rna_tf32(c2));
                c3 = __uint_as_float(rna_tf32(c3));
            } else {
                float b0 = aux[col], b1 = aux[col + 1];
                c0 += b0; c1 += b1; c2 += b0; c3 += b1;
            }
            *(float2*)(C + (size_t)r0 * ldC + col)       = make_float2(c0, c1);
            *(float2*)(C + (size_t)(r0 + 8) * ldC + col) = make_float2(c2, c3);
        }
    }
}

// ---------------- launch -----------------------------------------------------------
extern "C" void kernel_launch(void* const* d_in, const int* in_sizes, int n_in,
                              void* d_out, int out_size) {
    const float* x      = (const float*)d_in[0];   // [N, D]
    const float* w_gate = (const float*)d_in[1];   // [D, E]
    const float* w1     = (const float*)d_in[2];   // [E, D, H]
    const float* w2     = (const float*)d_in[3];   // [E, H, D]
    const float* w_proj = (const float*)d_in[4];   // [D, EMB]
    const float* b_proj = (const float*)d_in[5];   // [EMB]
    float* out = (float*)d_out;                    // [N, EMB]

    float *xt_p, *h_p, *y_p, *w1t_p, *w2t_p, *wpt_p;
    cudaGetSymbolAddress((void**)&xt_p, g_xt);
    cudaGetSymbolAddress((void**)&h_p, g_h);
    cudaGetSymbolAddress((void**)&y_p, g_y);
    cudaGetSymbolAddress((void**)&w1t_p, g_w1t);
    cudaGetSymbolAddress((void**)&w2t_p, g_w2t);
    cudaGetSymbolAddress((void**)&wpt_p, g_wpt);

    cudaFuncSetAttribute(gemm_mma<DIM, 0>,  cudaFuncAttributeMaxDynamicSharedMemorySize, SMEM_BYTES);
    cudaFuncSetAttribute(gemm_mma<KCAT, 1>, cudaFuncAttributeMaxDynamicSharedMemorySize, SMEM_BYTES);
    cudaFuncSetAttribute(gemm_mma<DIM, 2>,  cudaFuncAttributeMaxDynamicSharedMemorySize, SMEM_BYTES);

    // prep
    gate_kernel<<<N_TOK / 8, 256>>>(x, w_gate);
    round_x_kernel<<<(N_TOK * DIM / 4) / 256, 256>>>((const float4*)x, (float4*)xt_p);
    transpose_rna_kernel<<<dim3(HID / 32, DIM / 32, NEXP), dim3(32, 8)>>>(w1, w1t_p, DIM, HID);
    transpose_rna_kernel<<<dim3(DIM / 32, KCAT / 32, 1), dim3(32, 8)>>>(w2, w2t_p, KCAT, DIM);
    transpose_rna_kernel<<<dim3(EMBD / 32, DIM / 32, 1), dim3(32, 8)>>>(w_proj, wpt_p, DIM, EMBD);

    // GEMM1 (4 experts via grid.z): h[:, e*512+n] = rna(gate[:,e] * gelu(x @ w1[e]))
    gemm_mma<DIM, 0><<<dim3(HID / BN, N_TOK / BM, NEXP), 256, SMEM_BYTES>>>(
        xt_p, w1t_p, h_p, KCAT, nullptr, HID * DIM, HID);

    // GEMM2: y = rna(h @ concat(w2))   (K = 2048)
    gemm_mma<KCAT, 1><<<dim3(DIM / BN, N_TOK / BM, 1), 256, SMEM_BYTES>>>(
        h_p, w2t_p, y_p, DIM, nullptr, 0, 0);

    // proj: out = y @ w_proj + b
    gemm_mma<DIM, 2><<<dim3(EMBD / BN, N_TOK / BM, 1), 256, SMEM_BYTES>>>(
        y_p, wpt_p, out, EMBD, b_proj, 0, 0);
}

// round 4
// speedup vs baseline: 3.8802x; 1.6764x over previous
#include <cuda_runtime.h>
#include <math.h>
#include <cstdint>

// Problem dims
#define N_TOK 65536
#define DIM   256
#define NEXP  4
#define HID   512
#define EMBD  512
#define SLOTS (2 * N_TOK + NEXP * 128)   // 131584 compact rows (128-aligned per expert)

// ---------------- scratch (device globals) -------------------------------------
__device__ float g_xt[(size_t)N_TOK * DIM];          // tf32-rounded x
__device__ float g_h[(size_t)SLOTS * HID];           // compact gated hidden
__device__ float g_yc[(size_t)SLOTS * DIM];          // compact expert outputs
__device__ float g_y[(size_t)N_TOK * DIM];           // combined (rna'd)
__device__ float g_w1t[NEXP * HID * DIM];            // [e][H][D]
__device__ float g_w2t[NEXP * DIM * HID];            // [e][D][H]
__device__ float g_wpt[EMBD * DIM];                  // [EMB][D]

__device__ int   g_cnt[NEXP];
__device__ int   g_cnt2[NEXP];
__device__ int   g_off[NEXP + 1];
__device__ int2  g_te[N_TOK];        // (e1, e2)
__device__ float2 g_tg[N_TOK];       // (g1, g2)
__device__ int2  g_pos[N_TOK];       // slots of this token's 2 assignments
__device__ int   g_slot_tok[SLOTS];
__device__ float g_slot_gate[SLOTS];

// ---------------- helpers -------------------------------------------------------
__device__ __forceinline__ uint32_t smem_to_u32(const void* p) {
    uint32_t a;
    asm("{ .reg .u64 t; cvta.to.shared.u64 t, %1; cvt.u32.u64 %0, t; }" : "=r"(a) : "l"(p));
    return a;
}
__device__ __forceinline__ uint32_t rna_tf32(float f) {
    uint32_t r;
    asm("cvt.rna.tf32.f32 %0, %1;" : "=r"(r) : "f"(f));
    return r;
}
__device__ __forceinline__ void cp_async16(uint32_t dst, const void* src) {
    asm volatile("cp.async.cg.shared.global [%0], [%1], 16;"
                 :: "r"(dst), "l"(src) : "memory");
}
__device__ __forceinline__ void mma_tf32(float c[4], uint32_t a0, uint32_t a1,
                                         uint32_t a2, uint32_t a3,
                                         uint32_t b0, uint32_t b1) {
    asm volatile(
        "mma.sync.aligned.m16n8k8.row.col.f32.tf32.tf32.f32 "
        "{%0,%1,%2,%3}, {%4,%5,%6,%7}, {%8,%9}, {%0,%1,%2,%3};"
        : "+f"(c[0]), "+f"(c[1]), "+f"(c[2]), "+f"(c[3])
        : "r"(a0), "r"(a1), "r"(a2), "r"(a3), "r"(b0), "r"(b1));
}

// ---------------- small prep kernels ---------------------------------------------
__global__ void init_counts_kernel() {
    int t = threadIdx.x;
    if (t < NEXP) { g_cnt[t] = 0; g_cnt2[t] = 0; }
}

__global__ void slot_init_kernel() {
    int i = blockIdx.x * blockDim.x + threadIdx.x;
    if (i < SLOTS) { g_slot_tok[i] = 0; g_slot_gate[i] = 0.f; }
}

__global__ void round_x_kernel(const float4* __restrict__ in, float4* __restrict__ out) {
    size_t i = (size_t)blockIdx.x * blockDim.x + threadIdx.x;
    float4 v = in[i];
    uint4 r;
    r.x = rna_tf32(v.x); r.y = rna_tf32(v.y); r.z = rna_tf32(v.z); r.w = rna_tf32(v.w);
    *(uint4*)(out + i) = r;
}

__global__ void transpose_rna_kernel(const float* __restrict__ in, float* __restrict__ out,
                                     int K, int N) {
    __shared__ float t[32][33];
    int b = blockIdx.z;
    in  += (size_t)b * K * N;
    out += (size_t)b * K * N;
    int n0 = blockIdx.x * 32, k0 = blockIdx.y * 32;
    int tx = threadIdx.x, ty = threadIdx.y;  // 32 x 8
    #pragma unroll
    for (int j = 0; j < 32; j += 8)
        t[ty + j][tx] = in[(size_t)(k0 + ty + j) * N + n0 + tx];
    __syncthreads();
    #pragma unroll
    for (int j = 0; j < 32; j += 8)
        out[(size_t)(n0 + ty + j) * K + k0 + tx] = __uint_as_float(rna_tf32(t[tx][ty + j]));
}

// ---------------- gating + per-expert counting ------------------------------------
__global__ void gate_assign_kernel(const float* __restrict__ x, const float* __restrict__ wg) {
    __shared__ float sw[DIM * NEXP];
    __shared__ int bc[NEXP];
    int tid = threadIdx.x;
    for (int i = tid; i < DIM * NEXP; i += blockDim.x) sw[i] = wg[i];
    if (tid < NEXP) bc[tid] = 0;
    __syncthreads();
    int warp = tid >> 5, lane = tid & 31;
    int token = blockIdx.x * (blockDim.x >> 5) + warp;
    const float* xr = x + (size_t)token * DIM;
    float s0 = 0.f, s1 = 0.f, s2 = 0.f, s3 = 0.f;
    #pragma unroll
    for (int d = lane; d < DIM; d += 32) {
        float xv = xr[d];
        s0 += xv * sw[d * NEXP + 0];
        s1 += xv * sw[d * NEXP + 1];
        s2 += xv * sw[d * NEXP + 2];
        s3 += xv * sw[d * NEXP + 3];
    }
    #pragma unroll
    for (int o = 16; o > 0; o >>= 1) {
        s0 += __shfl_down_sync(0xffffffffu, s0, o);
        s1 += __shfl_down_sync(0xffffffffu, s1, o);
        s2 += __shfl_down_sync(0xffffffffu, s2, o);
        s3 += __shfl_down_sync(0xffffffffu, s3, o);
    }
    if (lane == 0) {
        float l[NEXP] = {s0, s1, s2, s3};
        int i1 = 0;
        #pragma unroll
        for (int e = 1; e < NEXP; e++) if (l[e] > l[i1]) i1 = e;
        int i2 = -1;
        #pragma unroll
        for (int e = 0; e < NEXP; e++) {
            if (e == i1) continue;
            if (i2 < 0 || l[e] > l[i2]) i2 = e;
        }
        float t = expf(l[i2] - l[i1]);
        float inv = 1.0f / (1.0f + t);
        g_te[token] = make_int2(i1, i2);
        g_tg[token] = make_float2(inv, t * inv);
        atomicAdd(&bc[i1], 1);
        atomicAdd(&bc[i2], 1);
    }
    __syncthreads();
    if (tid < NEXP) atomicAdd(&g_cnt[tid], bc[tid]);
}

__global__ void offsets_kernel() {
    if (threadIdx.x == 0) {
        int o = 0;
        g_off[0] = 0;
        #pragma unroll
        for (int e = 0; e < NEXP; e++) {
            o += (g_cnt[e] + 127) & ~127;
            g_off[e + 1] = o;
        }
    }
}

// ---------------- placement (warp-aggregated atomics) ------------------------------
__global__ void place_kernel() {
    int n = blockIdx.x * blockDim.x + threadIdx.x;
    int lane = threadIdx.x & 31;
    int2 te = g_te[n];
    float2 tg = g_tg[n];
    int p1 = 0, p2 = 0;
    unsigned lt = (1u << lane) - 1u;
    #pragma unroll
    for (int e = 0; e < NEXP; e++) {
        unsigned m1 = __ballot_sync(0xffffffffu, te.x == e);
        unsigned m2 = __ballot_sync(0xffffffffu, te.y == e);
        int tot = __popc(m1) + __popc(m2);
        int base = 0;
        if (lane == 0 && tot) base = atomicAdd(&g_cnt2[e], tot);
        base = __shfl_sync(0xffffffffu, base, 0);
        int off = g_off[e] + base;
        if (te.x == e) p1 = off + __popc(m1 & lt);
        if (te.y == e) p2 = off + __popc(m1) + __popc(m2 & lt);
    }
    g_slot_tok[p1] = n;  g_slot_gate[p1] = tg.x;
    g_slot_tok[p2] = n;  g_slot_gate[p2] = tg.y;
    g_pos[n] = make_int2(p1, p2);
}

// ---------------- mma.sync tf32 GEMM -----------------------------------------------
// MODE 0 (sparse GEMM1): A rows gathered via slot_tok from xt; epi rna(gate*gelu); C=h
// MODE 1 (sparse GEMM2): A = h compact; raw fp32 store; C=yc
// MODE 2 (dense proj):   A = y; epi + bias; C=out
#define BM 128
#define BN 128
#define BK 32
#define SA 36
#define TILE_F (128 * SA)
#define STAGE_F (2 * TILE_F)
#define SMEM_BYTES (2 * STAGE_F * 4)

template <int KDIM, int MODE>
__global__ void __launch_bounds__(256, 2) gemm_mma(
    const float* __restrict__ A,
    const float* __restrict__ Bt,
    float* __restrict__ C, int ldC,
    const float* __restrict__ aux,
    int bt_estride)
{
    extern __shared__ float sm[];
    const uint32_t smem_base = smem_to_u32(sm);

    const int tid = threadIdx.x;
    const int wid = tid >> 5, lane = tid & 31;
    const int gr = lane >> 2, gc = lane & 3;
    const int warpM = wid >> 2, warpN = wid & 3;
    const int n0 = blockIdx.x * BN;

    int e = 0;
    int row_base;
    if (MODE == 0 || MODE == 1) {
        row_base = blockIdx.y * BM;
        if (row_base >= g_off[NEXP]) return;
        e = (row_base >= g_off[1]) + (row_base >= g_off[2]) + (row_base >= g_off[3]);
    } else {
        row_base = blockIdx.y * BM;
    }

    const int NCH = KDIM / BK;
    const float* Bg = Bt + (size_t)e * bt_estride + (size_t)n0 * KDIM;

    // per-thread A source row (indirect for MODE 0)
    const int f_row = tid >> 1;
    const int f_cg0 = (tid & 1) * 4;
    const float* srcA_base;
    if (MODE == 0) {
        int tok = g_slot_tok[row_base + f_row];
        srcA_base = A + (size_t)tok * KDIM;
    } else {
        srcA_base = A + (size_t)(row_base + f_row) * KDIM;
    }
    const float* srcB_base = Bg + (size_t)f_row * KDIM;

    float acc[4][4][4];
    #pragma unroll
    for (int mi = 0; mi < 4; mi++)
        #pragma unroll
        for (int ni = 0; ni < 4; ni++)
            #pragma unroll
            for (int j = 0; j < 4; j++) acc[mi][ni][j] = 0.f;

    auto issue_stage = [&](int c) {
        const int s = c & 1;
        const uint32_t sb = smem_base + (uint32_t)s * (STAGE_F * 4);
        const int k0 = c * BK;
        const float* srcA = srcA_base + k0 + f_cg0 * 4;
        const float* srcB = srcB_base + k0 + f_cg0 * 4;
        const uint32_t dA = sb + f_row * (SA * 4) + f_cg0 * 16;
        const uint32_t dB = dA + TILE_F * 4;
        #pragma unroll
        for (int i = 0; i < 4; i++) cp_async16(dA + i * 16, srcA + i * 4);
        #pragma unroll
        for (int i = 0; i < 4; i++) cp_async16(dB + i * 16, srcB + i * 4);
        asm volatile("cp.async.commit_group;" ::: "memory");
    };

    issue_stage(0);

    for (int c = 0; c < NCH; c++) {
        if (c + 1 < NCH) {
            issue_stage(c + 1);
            asm volatile("cp.async.wait_group 1;" ::: "memory");
        } else {
            asm volatile("cp.async.wait_group 0;" ::: "memory");
        }
        __syncthreads();

        const float* As = sm + (c & 1) * STAGE_F;
        const float* Bs = As + TILE_F;
        const float* ap = As + (warpM * 64 + gr) * SA + gc;
        const float* bp = Bs + (warpN * 32 + gr) * SA + gc;

        #pragma unroll
        for (int kk = 0; kk < 4; kk++) {
            const float* apk = ap + kk * 8;
            const float* bpk = bp + kk * 8;
            uint32_t bf[4][2];
            #pragma unroll
            for (int ni = 0; ni < 4; ni++) {
                bf[ni][0] = __float_as_uint(bpk[ni * 8 * SA]);
                bf[ni][1] = __float_as_uint(bpk[ni * 8 * SA + 4]);
            }
            #pragma unroll
            for (int mi = 0; mi < 4; mi++) {
                uint32_t a0 = __float_as_uint(apk[mi * 16 * SA]);
                uint32_t a1 = __float_as_uint(apk[mi * 16 * SA + 8 * SA]);
                uint32_t a2 = __float_as_uint(apk[mi * 16 * SA + 4]);
                uint32_t a3 = __float_as_uint(apk[mi * 16 * SA + 8 * SA + 4]);
                #pragma unroll
                for (int ni = 0; ni < 4; ni++)
                    mma_tf32(acc[mi][ni], a0, a1, a2, a3, bf[ni][0], bf[ni][1]);
            }
        }
        __syncthreads();
    }

    // ---------------- epilogue ----------------
    #pragma unroll
    for (int mi = 0; mi < 4; mi++) {
        const int r0 = row_base + warpM * 64 + mi * 16 + gr;
        float g0 = 0.f, g1 = 0.f;
        if (MODE == 0) {
            g0 = g_slot_gate[r0];
            g1 = g_slot_gate[r0 + 8];
        }
        #pragma unroll
        for (int ni = 0; ni < 4; ni++) {
            const int col = n0 + warpN * 32 + ni * 8 + gc * 2;
            float c0 = acc[mi][ni][0], c1 = acc[mi][ni][1];
            float c2 = acc[mi][ni][2], c3 = acc[mi][ni][3];
            if (MODE == 0) {
                c0 = __uint_as_float(rna_tf32(g0 * (c0 * normcdff(c0))));
                c1 = __uint_as_float(rna_tf32(g0 * (c1 * normcdff(c1))));
                c2 = __uint_as_float(rna_tf32(g1 * (c2 * normcdff(c2))));
                c3 = __uint_as_float(rna_tf32(g1 * (c3 * normcdff(c3))));
            } else if (MODE == 2) {
                float b0 = aux[col], b1 = aux[col + 1];
                c0 += b0; c1 += b1; c2 += b0; c3 += b1;
            }
            *(float2*)(C + (size_t)r0 * ldC + col)       = make_float2(c0, c1);
            *(float2*)(C + (size_t)(r0 + 8) * ldC + col) = make_float2(c2, c3);
        }
    }
}

// ---------------- combine: y[n] = rna(yc[p1] + yc[p2]) -----------------------------
__global__ void combine_kernel(const float4* __restrict__ yc, float4* __restrict__ y) {
    int idx = blockIdx.x * blockDim.x + threadIdx.x;   // over N_TOK * 64
    int token = idx >> 6, c = idx & 63;
    int2 p = g_pos[token];
    float4 a = yc[(size_t)p.x * 64 + c];
    float4 b = yc[(size_t)p.y * 64 + c];
    float4 r;
    r.x = __uint_as_float(rna_tf32(a.x + b.x));
    r.y = __uint_as_float(rna_tf32(a.y + b.y));
    r.z = __uint_as_float(rna_tf32(a.z + b.z));
    r.w = __uint_as_float(rna_tf32(a.w + b.w));
    y[(size_t)token * 64 + c] = r;
}

// ---------------- launch -------------------------------------------------------------
extern "C" void kernel_launch(void* const* d_in, const int* in_sizes, int n_in,
                              void* d_out, int out_size) {
    const float* x      = (const float*)d_in[0];   // [N, D]
    const float* w_gate = (const float*)d_in[1];   // [D, E]
    const float* w1     = (const float*)d_in[2];   // [E, D, H]
    const float* w2     = (const float*)d_in[3];   // [E, H, D]
    const float* w_proj = (const float*)d_in[4];   // [D, EMB]
    const float* b_proj = (const float*)d_in[5];   // [EMB]
    float* out = (float*)d_out;                    // [N, EMB]

    float *xt_p, *h_p, *yc_p, *y_p, *w1t_p, *w2t_p, *wpt_p;
    cudaGetSymbolAddress((void**)&xt_p, g_xt);
    cudaGetSymbolAddress((void**)&h_p, g_h);
    cudaGetSymbolAddress((void**)&yc_p, g_yc);
    cudaGetSymbolAddress((void**)&y_p, g_y);
    cudaGetSymbolAddress((void**)&w1t_p, g_w1t);
    cudaGetSymbolAddress((void**)&w2t_p, g_w2t);
    cudaGetSymbolAddress((void**)&wpt_p, g_wpt);

    cudaFuncSetAttribute(gemm_mma<DIM, 0>, cudaFuncAttributeMaxDynamicSharedMemorySize, SMEM_BYTES);
    cudaFuncSetAttribute(gemm_mma<HID, 1>, cudaFuncAttributeMaxDynamicSharedMemorySize, SMEM_BYTES);
    cudaFuncSetAttribute(gemm_mma<DIM, 2>, cudaFuncAttributeMaxDynamicSharedMemorySize, SMEM_BYTES);

    const int MAX_TILES = SLOTS / BM;   // 1028

    // prep + routing
    init_counts_kernel<<<1, 32>>>();
    slot_init_kernel<<<(SLOTS + 255) / 256, 256>>>();
    round_x_kernel<<<(N_TOK * DIM / 4) / 256, 256>>>((const float4*)x, (float4*)xt_p);
    transpose_rna_kernel<<<dim3(HID / 32, DIM / 32, NEXP), dim3(32, 8)>>>(w1, w1t_p, DIM, HID);
    transpose_rna_kernel<<<dim3(DIM / 32, HID / 32, NEXP), dim3(32, 8)>>>(w2, w2t_p, HID, DIM);
    transpose_rna_kernel<<<dim3(EMBD / 32, DIM / 32, 1), dim3(32, 8)>>>(w_proj, wpt_p, DIM, EMBD);
    gate_assign_kernel<<<N_TOK / 8, 256>>>(x, w_gate);
    offsets_kernel<<<1, 32>>>();
    place_kernel<<<N_TOK / 256, 256>>>();

    // GEMM1 sparse: h[slot] = rna(gate * gelu(x[tok] @ w1[e]))
    gemm_mma<DIM, 0><<<dim3(HID / BN, MAX_TILES), 256, SMEM_BYTES>>>(
        xt_p, w1t_p, h_p, HID, nullptr, HID * DIM);

    // GEMM2 sparse: yc[slot] = h[slot] @ w2[e]^T   (raw fp32)
    gemm_mma<HID, 1><<<dim3(DIM / BN, MAX_TILES), 256, SMEM_BYTES>>>(
        h_p, w2t_p, yc_p, DIM, nullptr, DIM * HID);

    // combine: y = rna(yc[p1] + yc[p2])
    combine_kernel<<<(N_TOK * 64) / 256, 256>>>((const float4*)yc_p, (float4*)y_p);

    // proj: out = y @ w_proj + b
    gemm_mma<DIM, 2><<<dim3(EMBD / BN, N_TOK / BM), 256, SMEM_BYTES>>>(
        y_p, wpt_p, out, EMBD, b_proj, 0);
}

// round 5
// speedup vs baseline: 7.3470x; 1.8934x over previous
#include <cuda_runtime.h>
#include <cuda_fp16.h>
#include <math.h>
#include <cstdint>

// Problem dims
#define N_TOK 65536
#define DIM   256
#define NEXP  4
#define HID   512
#define EMBD  512
#define SLOTS (2 * N_TOK + NEXP * 128)   // 131584 compact rows (128-aligned per expert)

// ---------------- scratch (device globals) -------------------------------------
__device__ __align__(128) __half g_xh[(size_t)N_TOK * DIM];     // fp16 x
__device__ __align__(128) __half g_h[(size_t)SLOTS * HID];      // compact gated hidden (fp16)
__device__ __align__(128) float  g_yc[(size_t)SLOTS * DIM];     // compact expert outputs (fp32)
__device__ __align__(128) __half g_yh[(size_t)N_TOK * DIM];     // combined y (fp16)
__device__ __align__(128) __half g_w1t[NEXP * HID * DIM];       // [e][H][D]
__device__ __align__(128) __half g_w2t[NEXP * DIM * HID];       // [e][D][H]
__device__ __align__(128) __half g_wpt[EMBD * DIM];             // [EMB][D]

__device__ int    g_cnt[NEXP];
__device__ int    g_cnt2[NEXP];
__device__ int    g_off[NEXP + 1];
__device__ int2   g_te[N_TOK];
__device__ float2 g_tg[N_TOK];
__device__ int2   g_pos[N_TOK];
__device__ int    g_slot_tok[SLOTS];
__device__ float  g_slot_gate[SLOTS];

// ---------------- helpers -------------------------------------------------------
__device__ __forceinline__ uint32_t smem_to_u32(const void* p) {
    uint32_t a;
    asm("{ .reg .u64 t; cvta.to.shared.u64 t, %1; cvt.u32.u64 %0, t; }" : "=r"(a) : "l"(p));
    return a;
}
__device__ __forceinline__ void cp_async16(uint32_t dst, const void* src) {
    asm volatile("cp.async.cg.shared.global [%0], [%1], 16;"
                 :: "r"(dst), "l"(src) : "memory");
}
__device__ __forceinline__ void ldsm_x4(uint32_t& r0, uint32_t& r1, uint32_t& r2,
                                        uint32_t& r3, uint32_t addr) {
    asm volatile("ldmatrix.sync.aligned.m8n8.x4.shared.b16 {%0,%1,%2,%3}, [%4];"
                 : "=r"(r0), "=r"(r1), "=r"(r2), "=r"(r3) : "r"(addr));
}
__device__ __forceinline__ void mma_f16(float c[4], uint32_t a0, uint32_t a1,
                                        uint32_t a2, uint32_t a3,
                                        uint32_t b0, uint32_t b1) {
    asm volatile(
        "mma.sync.aligned.m16n8k16.row.col.f32.f16.f16.f32 "
        "{%0,%1,%2,%3}, {%4,%5,%6,%7}, {%8,%9}, {%0,%1,%2,%3};"
        : "+f"(c[0]), "+f"(c[1]), "+f"(c[2]), "+f"(c[3])
        : "r"(a0), "r"(a1), "r"(a2), "r"(a3), "r"(b0), "r"(b1));
}
__device__ __forceinline__ uint32_t h2raw(__half2 h) {
    return *reinterpret_cast<uint32_t*>(&h);
}
#define SWZ(off) ((off) ^ (((off) >> 3) & 0x70))

// ---------------- small prep kernels ---------------------------------------------
__global__ void init_counts_kernel() {
    int t = threadIdx.x;
    if (t < NEXP) { g_cnt[t] = 0; g_cnt2[t] = 0; }
}
__global__ void slot_init_kernel() {
    int i = blockIdx.x * blockDim.x + threadIdx.x;
    if (i < SLOTS) { g_slot_tok[i] = 0; g_slot_gate[i] = 0.f; }
}
__global__ void tohalf_kernel(const float4* __restrict__ in, uint2* __restrict__ out) {
    size_t i = (size_t)blockIdx.x * blockDim.x + threadIdx.x;
    float4 v = in[i];
    __half2 h0 = __floats2half2_rn(v.x, v.y);
    __half2 h1 = __floats2half2_rn(v.z, v.w);
    out[i] = make_uint2(h2raw(h0), h2raw(h1));
}
__global__ void transpose_half_kernel(const float* __restrict__ in, __half* __restrict__ out,
                                      int K, int N) {
    __shared__ float t[32][33];
    int b = blockIdx.z;
    in  += (size_t)b * K * N;
    out += (size_t)b * K * N;
    int n0 = blockIdx.x * 32, k0 = blockIdx.y * 32;
    int tx = threadIdx.x, ty = threadIdx.y;  // 32 x 8
    #pragma unroll
    for (int j = 0; j < 32; j += 8)
        t[ty + j][tx] = in[(size_t)(k0 + ty + j) * N + n0 + tx];
    __syncthreads();
    #pragma unroll
    for (int j = 0; j < 32; j += 8)
        out[(size_t)(n0 + ty + j) * K + k0 + tx] = __float2half_rn(t[tx][ty + j]);
}

// ---------------- gating + per-expert counting ------------------------------------
__global__ void gate_assign_kernel(const float* __restrict__ x, const float* __restrict__ wg) {
    __shared__ float sw[DIM * NEXP];
    __shared__ int bc[NEXP];
    int tid = threadIdx.x;
    for (int i = tid; i < DIM * NEXP; i += blockDim.x) sw[i] = wg[i];
    if (tid < NEXP) bc[tid] = 0;
    __syncthreads();
    int warp = tid >> 5, lane = tid & 31;
    int token = blockIdx.x * (blockDim.x >> 5) + warp;
    const float* xr = x + (size_t)token * DIM;
    float s0 = 0.f, s1 = 0.f, s2 = 0.f, s3 = 0.f;
    #pragma unroll
    for (int d = lane; d < DIM; d += 32) {
        float xv = xr[d];
        s0 += xv * sw[d * NEXP + 0];
        s1 += xv * sw[d * NEXP + 1];
        s2 += xv * sw[d * NEXP + 2];
        s3 += xv * sw[d * NEXP + 3];
    }
    #pragma unroll
    for (int o = 16; o > 0; o >>= 1) {
        s0 += __shfl_down_sync(0xffffffffu, s0, o);
        s1 += __shfl_down_sync(0xffffffffu, s1, o);
        s2 += __shfl_down_sync(0xffffffffu, s2, o);
        s3 += __shfl_down_sync(0xffffffffu, s3, o);
    }
    if (lane == 0) {
        float l[NEXP] = {s0, s1, s2, s3};
        int i1 = 0;
        #pragma unroll
        for (int e = 1; e < NEXP; e++) if (l[e] > l[i1]) i1 = e;
        int i2 = -1;
        #pragma unroll
        for (int e = 0; e < NEXP; e++) {
            if (e == i1) continue;
            if (i2 < 0 || l[e] > l[i2]) i2 = e;
        }
        float t = expf(l[i2] - l[i1]);
        float inv = 1.0f / (1.0f + t);
        g_te[token] = make_int2(i1, i2);
        g_tg[token] = make_float2(inv, t * inv);
        atomicAdd(&bc[i1], 1);
        atomicAdd(&bc[i2], 1);
    }
    __syncthreads();
    if (tid < NEXP) atomicAdd(&g_cnt[tid], bc[tid]);
}

__global__ void offsets_kernel() {
    if (threadIdx.x == 0) {
        int o = 0;
        g_off[0] = 0;
        #pragma unroll
        for (int e = 0; e < NEXP; e++) {
            o += (g_cnt[e] + 127) & ~127;
            g_off[e + 1] = o;
        }
    }
}

__global__ void place_kernel() {
    int n = blockIdx.x * blockDim.x + threadIdx.x;
    int lane = threadIdx.x & 31;
    int2 te = g_te[n];
    float2 tg = g_tg[n];
    int p1 = 0, p2 = 0;
    unsigned lt = (1u << lane) - 1u;
    #pragma unroll
    for (int e = 0; e < NEXP; e++) {
        unsigned m1 = __ballot_sync(0xffffffffu, te.x == e);
        unsigned m2 = __ballot_sync(0xffffffffu, te.y == e);
        int tot = __popc(m1) + __popc(m2);
        int base = 0;
        if (lane == 0 && tot) base = atomicAdd(&g_cnt2[e], tot);
        base = __shfl_sync(0xffffffffu, base, 0);
        int off = g_off[e] + base;
        if (te.x == e) p1 = off + __popc(m1 & lt);
        if (te.y == e) p2 = off + __popc(m1) + __popc(m2 & lt);
    }
    g_slot_tok[p1] = n;  g_slot_gate[p1] = tg.x;
    g_slot_tok[p2] = n;  g_slot_gate[p2] = tg.y;
    g_pos[n] = make_int2(p1, p2);
}

// ---------------- fp16 mma GEMM -----------------------------------------------------
// MODE 0 (sparse GEMM1): A rows gathered via slot_tok from xh; epi gate*gelu -> fp16 h
// MODE 1 (sparse GEMM2): A = h compact fp16; raw fp32 -> yc
// MODE 2 (dense proj):   A = yh; epi + bias -> fp32 out
#define BM 128
#define BN 128
#define BK 64                       // fp16 elements per chunk; 128 B per tile row
#define TILE_B (128 * 128)          // 16384 bytes per tile
#define STAGE_B (2 * TILE_B)        // A + B = 32768
#define SMEM_BYTES (2 * STAGE_B)    // double buffered = 65536

template <int KDIM, int MODE>
__global__ void __launch_bounds__(256, 2) gemm_mma(
    const __half* __restrict__ A,
    const __half* __restrict__ Bt,
    void* __restrict__ Cv, int ldC,
    const float* __restrict__ aux,
    int bt_estride)
{
    extern __shared__ char smc[];
    const uint32_t smem_base = smem_to_u32(smc);

    const int tid = threadIdx.x;
    const int wid = tid >> 5, lane = tid & 31;
    const int gr = lane >> 2, gc = lane & 3;
    const int warpM = wid >> 2, warpN = wid & 3;
    const int n0 = blockIdx.x * BN;

    int e = 0;
    const int row_base = blockIdx.y * BM;
    if (MODE == 0 || MODE == 1) {
        if (row_base >= g_off[NEXP]) return;
        e = (row_base >= g_off[1]) + (row_base >= g_off[2]) + (row_base >= g_off[3]);
    }

    const int NCH = KDIM / BK;

    // per-thread staging source rows
    const int f_row = tid >> 1;                 // 0..127
    const int f_cg0 = (tid & 1) * 4;            // 16B-chunk start within 128B row
    const __half* srcA_base;
    if (MODE == 0) {
        int tok = g_slot_tok[row_base + f_row];
        srcA_base = A + (size_t)tok * KDIM;
    } else {
        srcA_base = A + (size_t)(row_base + f_row) * KDIM;
    }
    const __half* srcB_base = Bt + (size_t)e * bt_estride + (size_t)(n0 + f_row) * KDIM;

    float acc[4][4][4];
    #pragma unroll
    for (int mi = 0; mi < 4; mi++)
        #pragma unroll
        for (int ni = 0; ni < 4; ni++)
            #pragma unroll
            for (int j = 0; j < 4; j++) acc[mi][ni][j] = 0.f;

    auto issue_stage = [&](int c) {
        const uint32_t sb = smem_base + (uint32_t)(c & 1) * STAGE_B;
        const __half* srcA = srcA_base + c * BK + f_cg0 * 8;
        const __half* srcB = srcB_base + c * BK + f_cg0 * 8;
        const uint32_t dA = sb + SWZ(f_row * 128 + f_cg0 * 16);
        // SWZ only permutes bits [6:4]; chunks f_cg0..f_cg0+3 stay within one XOR class each
        #pragma unroll
        for (int i = 0; i < 4; i++)
            cp_async16(sb + SWZ(f_row * 128 + (f_cg0 + i) * 16), srcA + i * 8);
        #pragma unroll
        for (int i = 0; i < 4; i++)
            cp_async16(sb + TILE_B + SWZ(f_row * 128 + (f_cg0 + i) * 16), srcB + i * 8);
        asm volatile("cp.async.commit_group;" ::: "memory");
        (void)dA;
    };

    issue_stage(0);

    // ldmatrix lane-address components (byte offsets within tile, pre-swizzle)
    const int a_row = warpM * 64 + (lane & 15);          // + mi*16
    const int a_kb  = (lane >> 4) * 16;                  // k-half byte offset
    const int b_row = warpN * 32 + ((lane >> 4) << 3) + (lane & 7);  // + bj*16
    const int b_kb  = ((lane >> 3) & 1) * 16;

    for (int c = 0; c < NCH; c++) {
        if (c + 1 < NCH) {
            issue_stage(c + 1);
            asm volatile("cp.async.wait_group 1;" ::: "memory");
        } else {
            asm volatile("cp.async.wait_group 0;" ::: "memory");
        }
        __syncthreads();

        const uint32_t As = smem_base + (uint32_t)(c & 1) * STAGE_B;
        const uint32_t Bs = As + TILE_B;

        #pragma unroll
        for (int ks = 0; ks < BK / 16; ks++) {
            const int kb = ks * 32;
            uint32_t af[4][4], bf[4][2];
            #pragma unroll
            for (int mi = 0; mi < 4; mi++)
                ldsm_x4(af[mi][0], af[mi][1], af[mi][2], af[mi][3],
                        As + SWZ((a_row + mi * 16) * 128 + kb + a_kb));
            #pragma unroll
            for (int bj = 0; bj < 2; bj++)
                ldsm_x4(bf[bj * 2][0], bf[bj * 2][1], bf[bj * 2 + 1][0], bf[bj * 2 + 1][1],
                        Bs + SWZ((b_row + bj * 16) * 128 + kb + b_kb));
            #pragma unroll
            for (int mi = 0; mi < 4; mi++)
                #pragma unroll
                for (int ni = 0; ni < 4; ni++)
                    mma_f16(acc[mi][ni], af[mi][0], af[mi][1], af[mi][2], af[mi][3],
                            bf[ni][0], bf[ni][1]);
        }
        __syncthreads();
    }

    // ---------------- epilogue ----------------
    #pragma unroll
    for (int mi = 0; mi < 4; mi++) {
        const int r0 = row_base + warpM * 64 + mi * 16 + gr;
        float g0 = 0.f, g1 = 0.f;
        if (MODE == 0) {
            g0 = g_slot_gate[r0];
            g1 = g_slot_gate[r0 + 8];
        }
        #pragma unroll
        for (int ni = 0; ni < 4; ni++) {
            const int col = n0 + warpN * 32 + ni * 8 + gc * 2;
            float c0 = acc[mi][ni][0], c1 = acc[mi][ni][1];
            float c2 = acc[mi][ni][2], c3 = acc[mi][ni][3];
            if (MODE == 0) {
                __half* Ch = (__half*)Cv;
                __half2 h0 = __floats2half2_rn(g0 * (c0 * normcdff(c0)),
                                               g0 * (c1 * normcdff(c1)));
                __half2 h1 = __floats2half2_rn(g1 * (c2 * normcdff(c2)),
                                               g1 * (c3 * normcdff(c3)));
                *(__half2*)(Ch + (size_t)r0 * ldC + col)       = h0;
                *(__half2*)(Ch + (size_t)(r0 + 8) * ldC + col) = h1;
            } else if (MODE == 1) {
                float* Cf = (float*)Cv;
                *(float2*)(Cf + (size_t)r0 * ldC + col)       = make_float2(c0, c1);
                *(float2*)(Cf + (size_t)(r0 + 8) * ldC + col) = make_float2(c2, c3);
            } else {
                float* Cf = (float*)Cv;
                float b0 = aux[col], b1 = aux[col + 1];
                *(float2*)(Cf + (size_t)r0 * ldC + col)       = make_float2(c0 + b0, c1 + b1);
                *(float2*)(Cf + (size_t)(r0 + 8) * ldC + col) = make_float2(c2 + b0, c3 + b1);
            }
        }
    }
}

// ---------------- combine: yh[n] = fp16(yc[p1] + yc[p2]) ----------------------------
__global__ void combine_kernel(const float4* __restrict__ yc, uint2* __restrict__ yh) {
    int idx = blockIdx.x * blockDim.x + threadIdx.x;   // over N_TOK * 64
    int token = idx >> 6, c = idx & 63;
    int2 p = g_pos[token];
    float4 a = yc[(size_t)p.x * 64 + c];
    float4 b = yc[(size_t)p.y * 64 + c];
    __half2 h0 = __floats2half2_rn(a.x + b.x, a.y + b.y);
    __half2 h1 = __floats2half2_rn(a.z + b.z, a.w + b.w);
    yh[(size_t)token * 64 + c] = make_uint2(h2raw(h0), h2raw(h1));
}

// ---------------- launch -------------------------------------------------------------
extern "C" void kernel_launch(void* const* d_in, const int* in_sizes, int n_in,
                              void* d_out, int out_size) {
    const float* x      = (const float*)d_in[0];   // [N, D]
    const float* w_gate = (const float*)d_in[1];   // [D, E]
    const float* w1     = (const float*)d_in[2];   // [E, D, H]
    const float* w2     = (const float*)d_in[3];   // [E, H, D]
    const float* w_proj = (const float*)d_in[4];   // [D, EMB]
    const float* b_proj = (const float*)d_in[5];   // [EMB]
    float* out = (float*)d_out;                    // [N, EMB]

    __half *xh_p, *h_p, *yh_p, *w1t_p, *w2t_p, *wpt_p;
    float *yc_p;
    cudaGetSymbolAddress((void**)&xh_p, g_xh);
    cudaGetSymbolAddress((void**)&h_p, g_h);
    cudaGetSymbolAddress((void**)&yc_p, g_yc);
    cudaGetSymbolAddress((void**)&yh_p, g_yh);
    cudaGetSymbolAddress((void**)&w1t_p, g_w1t);
    cudaGetSymbolAddress((void**)&w2t_p, g_w2t);
    cudaGetSymbolAddress((void**)&wpt_p, g_wpt);

    cudaFuncSetAttribute(gemm_mma<DIM, 0>, cudaFuncAttributeMaxDynamicSharedMemorySize, SMEM_BYTES);
    cudaFuncSetAttribute(gemm_mma<HID, 1>, cudaFuncAttributeMaxDynamicSharedMemorySize, SMEM_BYTES);
    cudaFuncSetAttribute(gemm_mma<DIM, 2>, cudaFuncAttributeMaxDynamicSharedMemorySize, SMEM_BYTES);

    const int MAX_TILES = SLOTS / BM;   // 1028

    // prep + routing
    init_counts_kernel<<<1, 32>>>();
    slot_init_kernel<<<(SLOTS + 255) / 256, 256>>>();
    tohalf_kernel<<<(N_TOK * DIM / 4) / 256, 256>>>((const float4*)x, (uint2*)xh_p);
    transpose_half_kernel<<<dim3(HID / 32, DIM / 32, NEXP), dim3(32, 8)>>>(w1, w1t_p, DIM, HID);
    transpose_half_kernel<<<dim3(DIM / 32, HID / 32, NEXP), dim3(32, 8)>>>(w2, w2t_p, HID, DIM);
    transpose_half_kernel<<<dim3(EMBD / 32, DIM / 32, 1), dim3(32, 8)>>>(w_proj, wpt_p, DIM, EMBD);
    gate_assign_kernel<<<N_TOK / 8, 256>>>(x, w_gate);
    offsets_kernel<<<1, 32>>>();
    place_kernel<<<N_TOK / 256, 256>>>();

    // GEMM1 sparse: h[slot] = fp16(gate * gelu(x[tok] @ w1[e]))
    gemm_mma<DIM, 0><<<dim3(HID / BN, MAX_TILES), 256, SMEM_BYTES>>>(
        xh_p, w1t_p, h_p, HID, nullptr, HID * DIM);

    // GEMM2 sparse: yc[slot] = h[slot] @ w2[e]^T   (fp32)
    gemm_mma<HID, 1><<<dim3(DIM / BN, MAX_TILES), 256, SMEM_BYTES>>>(
        h_p, w2t_p, yc_p, DIM, nullptr, DIM * HID);

    // combine: yh = fp16(yc[p1] + yc[p2])
    combine_kernel<<<(N_TOK * 64) / 256, 256>>>((const float4*)yc_p, (uint2*)yh_p);

    // proj: out = yh @ w_proj + b
    gemm_mma<DIM, 2><<<dim3(EMBD / BN, N_TOK / BM), 256, SMEM_BYTES>>>(
        yh_p, wpt_p, out, EMBD, b_proj, 0);
}

// round 6
// speedup vs baseline: 7.3765x; 1.0040x over previous
#include <cuda_runtime.h>
#include <cuda_fp16.h>
#include <math.h>
#include <cstdint>

// Problem dims
#define N_TOK 65536
#define DIM   256
#define NEXP  4
#define HID   512
#define EMBD  512
#define SLOTS (2 * N_TOK + NEXP * 128)   // 131584 compact rows (128-aligned per expert)

// ---------------- scratch (device globals) -------------------------------------
__device__ __align__(128) __half g_xh[(size_t)N_TOK * DIM];     // fp16 x
__device__ __align__(128) __half g_h[(size_t)SLOTS * HID];      // compact gated hidden (fp16)
__device__ __align__(128) float  g_y[(size_t)N_TOK * DIM];      // combined y (fp32, RED target)
__device__ __align__(128) __half g_yh[(size_t)N_TOK * DIM];     // y in fp16 for proj
__device__ __align__(128) __half g_w1t[NEXP * HID * DIM];       // [e][H][D]
__device__ __align__(128) __half g_w2t[NEXP * DIM * HID];       // [e][D][H]
__device__ __align__(128) __half g_wpt[EMBD * DIM];             // [EMB][D]

__device__ int    g_cnt[NEXP];
__device__ int    g_cnt2[NEXP];
__device__ int    g_off[NEXP + 1];
__device__ int2   g_te[N_TOK];
__device__ float2 g_tg[N_TOK];
__device__ int    g_slot_tok[SLOTS];
__device__ float  g_slot_gate[SLOTS];

// ---------------- helpers -------------------------------------------------------
__device__ __forceinline__ uint32_t smem_to_u32(const void* p) {
    uint32_t a;
    asm("{ .reg .u64 t; cvta.to.shared.u64 t, %1; cvt.u32.u64 %0, t; }" : "=r"(a) : "l"(p));
    return a;
}
__device__ __forceinline__ void cp_async16(uint32_t dst, const void* src) {
    asm volatile("cp.async.cg.shared.global [%0], [%1], 16;"
                 :: "r"(dst), "l"(src) : "memory");
}
__device__ __forceinline__ void ldsm_x4(uint32_t& r0, uint32_t& r1, uint32_t& r2,
                                        uint32_t& r3, uint32_t addr) {
    asm volatile("ldmatrix.sync.aligned.m8n8.x4.shared.b16 {%0,%1,%2,%3}, [%4];"
                 : "=r"(r0), "=r"(r1), "=r"(r2), "=r"(r3) : "r"(addr));
}
__device__ __forceinline__ void mma_f16(float c[4], uint32_t a0, uint32_t a1,
                                        uint32_t a2, uint32_t a3,
                                        uint32_t b0, uint32_t b1) {
    asm volatile(
        "mma.sync.aligned.m16n8k16.row.col.f32.f16.f16.f32 "
        "{%0,%1,%2,%3}, {%4,%5,%6,%7}, {%8,%9}, {%0,%1,%2,%3};"
        : "+f"(c[0]), "+f"(c[1]), "+f"(c[2]), "+f"(c[3])
        : "r"(a0), "r"(a1), "r"(a2), "r"(a3), "r"(b0), "r"(b1));
}
__device__ __forceinline__ uint32_t h2raw(__half2 h) {
    return *reinterpret_cast<uint32_t*>(&h);
}
#define SWZ(off) ((off) ^ (((off) >> 3) & 0x70))

// ---------------- small prep kernels ---------------------------------------------
__global__ void init_counts_kernel() {
    int t = threadIdx.x;
    if (t < NEXP) { g_cnt[t] = 0; g_cnt2[t] = 0; }
}
__global__ void slot_init_kernel() {
    int i = blockIdx.x * blockDim.x + threadIdx.x;
    if (i < SLOTS) { g_slot_tok[i] = 0; g_slot_gate[i] = 0.f; }
}
__global__ void transpose_half_kernel(const float* __restrict__ in, __half* __restrict__ out,
                                      int K, int N) {
    __shared__ float t[32][33];
    int b = blockIdx.z;
    in  += (size_t)b * K * N;
    out += (size_t)b * K * N;
    int n0 = blockIdx.x * 32, k0 = blockIdx.y * 32;
    int tx = threadIdx.x, ty = threadIdx.y;  // 32 x 8
    #pragma unroll
    for (int j = 0; j < 32; j += 8)
        t[ty + j][tx] = in[(size_t)(k0 + ty + j) * N + n0 + tx];
    __syncthreads();
    #pragma unroll
    for (int j = 0; j < 32; j += 8)
        out[(size_t)(n0 + ty + j) * K + k0 + tx] = __float2half_rn(t[tx][ty + j]);
}
__global__ void tohalf_y_kernel(const float4* __restrict__ yf, uint2* __restrict__ yh) {
    size_t i = (size_t)blockIdx.x * blockDim.x + threadIdx.x;
    float4 v = yf[i];
    __half2 h0 = __floats2half2_rn(v.x, v.y);
    __half2 h1 = __floats2half2_rn(v.z, v.w);
    yh[i] = make_uint2(h2raw(h0), h2raw(h1));
}

// ---------------- gating + counting + fused x->fp16 ---------------------------------
__global__ void gate_assign_kernel(const float* __restrict__ x, const float* __restrict__ wg,
                                   __half* __restrict__ xh) {
    __shared__ float sw[DIM * NEXP];
    __shared__ int bc[NEXP];
    int tid = threadIdx.x;
    for (int i = tid; i < DIM * NEXP; i += blockDim.x) sw[i] = wg[i];
    if (tid < NEXP) bc[tid] = 0;
    __syncthreads();
    int warp = tid >> 5, lane = tid & 31;
    int token = blockIdx.x * (blockDim.x >> 5) + warp;
    const float* xr = x + (size_t)token * DIM;
    __half* xo = xh + (size_t)token * DIM;
    float s0 = 0.f, s1 = 0.f, s2 = 0.f, s3 = 0.f;
    #pragma unroll
    for (int d = lane; d < DIM; d += 32) {
        float xv = xr[d];
        xo[d] = __float2half_rn(xv);
        s0 += xv * sw[d * NEXP + 0];
        s1 += xv * sw[d * NEXP + 1];
        s2 += xv * sw[d * NEXP + 2];
        s3 += xv * sw[d * NEXP + 3];
    }
    #pragma unroll
    for (int o = 16; o > 0; o >>= 1) {
        s0 += __shfl_down_sync(0xffffffffu, s0, o);
        s1 += __shfl_down_sync(0xffffffffu, s1, o);
        s2 += __shfl_down_sync(0xffffffffu, s2, o);
        s3 += __shfl_down_sync(0xffffffffu, s3, o);
    }
    if (lane == 0) {
        float l[NEXP] = {s0, s1, s2, s3};
        int i1 = 0;
        #pragma unroll
        for (int e = 1; e < NEXP; e++) if (l[e] > l[i1]) i1 = e;
        int i2 = -1;
        #pragma unroll
        for (int e = 0; e < NEXP; e++) {
            if (e == i1) continue;
            if (i2 < 0 || l[e] > l[i2]) i2 = e;
        }
        float t = expf(l[i2] - l[i1]);
        float inv = 1.0f / (1.0f + t);
        g_te[token] = make_int2(i1, i2);
        g_tg[token] = make_float2(inv, t * inv);
        atomicAdd(&bc[i1], 1);
        atomicAdd(&bc[i2], 1);
    }
    __syncthreads();
    if (tid < NEXP) atomicAdd(&g_cnt[tid], bc[tid]);
}

__global__ void offsets_kernel() {
    if (threadIdx.x == 0) {
        int o = 0;
        g_off[0] = 0;
        #pragma unroll
        for (int e = 0; e < NEXP; e++) {
            o += (g_cnt[e] + 127) & ~127;
            g_off[e + 1] = o;
        }
    }
}

__global__ void place_kernel() {
    int n = blockIdx.x * blockDim.x + threadIdx.x;
    int lane = threadIdx.x & 31;
    int2 te = g_te[n];
    float2 tg = g_tg[n];
    int p1 = 0, p2 = 0;
    unsigned lt = (1u << lane) - 1u;
    #pragma unroll
    for (int e = 0; e < NEXP; e++) {
        unsigned m1 = __ballot_sync(0xffffffffu, te.x == e);
        unsigned m2 = __ballot_sync(0xffffffffu, te.y == e);
        int tot = __popc(m1) + __popc(m2);
        int base = 0;
        if (lane == 0 && tot) base = atomicAdd(&g_cnt2[e], tot);
        base = __shfl_sync(0xffffffffu, base, 0);
        int off = g_off[e] + base;
        if (te.x == e) p1 = off + __popc(m1 & lt);
        if (te.y == e) p2 = off + __popc(m1) + __popc(m2 & lt);
    }
    g_slot_tok[p1] = n;  g_slot_gate[p1] = tg.x;
    g_slot_tok[p2] = n;  g_slot_gate[p2] = tg.y;
}

// ---------------- fp16 mma GEMM, 3-stage cp.async ring -----------------------------
// MODE 0 (sparse GEMM1): A gathered via slot_tok from xh; epi gate*gelu -> fp16 h
// MODE 1 (sparse GEMM2): A = h compact fp16; epi: RED.add fp32 -> y[token]
// MODE 2 (dense proj):   A = yh; epi + bias -> fp32 out
#define BM 128
#define BN 128
#define BK 64
#define TILE_B (128 * 128)          // 16384 bytes per operand tile
#define STAGE_B (2 * TILE_B)        // A + B = 32768
#define NSTAGE 3
#define SMEM_BYTES (NSTAGE * STAGE_B)   // 98304

template <int KDIM, int MODE>
__global__ void __launch_bounds__(256, 2) gemm_mma(
    const __half* __restrict__ A,
    const __half* __restrict__ Bt,
    void* __restrict__ Cv, int ldC,
    const float* __restrict__ aux,
    int bt_estride)
{
    extern __shared__ char smc[];
    const uint32_t smem_base = smem_to_u32(smc);

    const int tid = threadIdx.x;
    const int wid = tid >> 5, lane = tid & 31;
    const int gr = lane >> 2, gc = lane & 3;
    const int warpM = wid >> 2, warpN = wid & 3;
    const int n0 = blockIdx.x * BN;

    int e = 0;
    const int row_base = blockIdx.y * BM;
    if (MODE == 0 || MODE == 1) {
        if (row_base >= g_off[NEXP]) return;
        e = (row_base >= g_off[1]) + (row_base >= g_off[2]) + (row_base >= g_off[3]);
    }

    const int NCH = KDIM / BK;

    // per-thread staging source rows
    const int f_row = tid >> 1;                 // 0..127
    const int f_cg0 = (tid & 1) * 4;            // 16B-chunk start within 128B row
    const __half* srcA_base;
    if (MODE == 0) {
        int tok = g_slot_tok[row_base + f_row];
        srcA_base = A + (size_t)tok * KDIM;
    } else {
        srcA_base = A + (size_t)(row_base + f_row) * KDIM;
    }
    const __half* srcB_base = Bt + (size_t)e * bt_estride + (size_t)(n0 + f_row) * KDIM;

    float acc[4][4][4];
    #pragma unroll
    for (int mi = 0; mi < 4; mi++)
        #pragma unroll
        for (int ni = 0; ni < 4; ni++)
            #pragma unroll
            for (int j = 0; j < 4; j++) acc[mi][ni][j] = 0.f;

    auto issue_stage = [&](int c) {
        const uint32_t sb = smem_base + (uint32_t)(c % NSTAGE) * STAGE_B;
        const __half* srcA = srcA_base + c * BK + f_cg0 * 8;
        const __half* srcB = srcB_base + c * BK + f_cg0 * 8;
        #pragma unroll
        for (int i = 0; i < 4; i++)
            cp_async16(sb + SWZ(f_row * 128 + (f_cg0 + i) * 16), srcA + i * 8);
        #pragma unroll
        for (int i = 0; i < 4; i++)
            cp_async16(sb + TILE_B + SWZ(f_row * 128 + (f_cg0 + i) * 16), srcB + i * 8);
        asm volatile("cp.async.commit_group;" ::: "memory");
    };

    issue_stage(0);
    issue_stage(1);

    // ldmatrix lane-address components (byte offsets within tile, pre-swizzle)
    const int a_row = warpM * 64 + (lane & 15);
    const int a_kb  = (lane >> 4) * 16;
    const int b_row = warpN * 32 + ((lane >> 4) << 3) + (lane & 7);
    const int b_kb  = ((lane >> 3) & 1) * 16;

    for (int c = 0; c < NCH; c++) {
        if (c == NCH - 1)
            asm volatile("cp.async.wait_group 0;" ::: "memory");
        else
            asm volatile("cp.async.wait_group 1;" ::: "memory");
        __syncthreads();

        if (c + 2 < NCH) issue_stage(c + 2);   // overwrites slot of chunk c-1 (consumed)

        const uint32_t As = smem_base + (uint32_t)(c % NSTAGE) * STAGE_B;
        const uint32_t Bs = As + TILE_B;

        #pragma unroll
        for (int ks = 0; ks < BK / 16; ks++) {
            const int kb = ks * 32;
            uint32_t af[4][4], bf[4][2];
            #pragma unroll
            for (int mi = 0; mi < 4; mi++)
                ldsm_x4(af[mi][0], af[mi][1], af[mi][2], af[mi][3],
                        As + SWZ((a_row + mi * 16) * 128 + kb + a_kb));
            #pragma unroll
            for (int bj = 0; bj < 2; bj++)
                ldsm_x4(bf[bj * 2][0], bf[bj * 2][1], bf[bj * 2 + 1][0], bf[bj * 2 + 1][1],
                        Bs + SWZ((b_row + bj * 16) * 128 + kb + b_kb));
            #pragma unroll
            for (int mi = 0; mi < 4; mi++)
                #pragma unroll
                for (int ni = 0; ni < 4; ni++)
                    mma_f16(acc[mi][ni], af[mi][0], af[mi][1], af[mi][2], af[mi][3],
                            bf[ni][0], bf[ni][1]);
        }
    }

    // ---------------- epilogue ----------------
    #pragma unroll
    for (int mi = 0; mi < 4; mi++) {
        const int r0 = row_base + warpM * 64 + mi * 16 + gr;
        float g0 = 0.f, g1 = 0.f;
        int tok0 = 0, tok1 = 0;
        if (MODE == 0) {
            g0 = g_slot_gate[r0];
            g1 = g_slot_gate[r0 + 8];
        } else if (MODE == 1) {
            tok0 = g_slot_tok[r0];
            tok1 = g_slot_tok[r0 + 8];
        }
        #pragma unroll
        for (int ni = 0; ni < 4; ni++) {
            const int col = n0 + warpN * 32 + ni * 8 + gc * 2;
            float c0 = acc[mi][ni][0], c1 = acc[mi][ni][1];
            float c2 = acc[mi][ni][2], c3 = acc[mi][ni][3];
            if (MODE == 0) {
                __half* Ch = (__half*)Cv;
                __half2 h0 = __floats2half2_rn(g0 * (c0 * normcdff(c0)),
                                               g0 * (c1 * normcdff(c1)));
                __half2 h1 = __floats2half2_rn(g1 * (c2 * normcdff(c2)),
                                               g1 * (c3 * normcdff(c3)));
                *(__half2*)(Ch + (size_t)r0 * ldC + col)       = h0;
                *(__half2*)(Ch + (size_t)(r0 + 8) * ldC + col) = h1;
            } else if (MODE == 1) {
                float* Yf = (float*)Cv;
                atomicAdd(Yf + (size_t)tok0 * ldC + col,     c0);
                atomicAdd(Yf + (size_t)tok0 * ldC + col + 1, c1);
                atomicAdd(Yf + (size_t)tok1 * ldC + col,     c2);
                atomicAdd(Yf + (size_t)tok1 * ldC + col + 1, c3);
            } else {
                float* Cf = (float*)Cv;
                float b0 = aux[col], b1 = aux[col + 1];
                *(float2*)(Cf + (size_t)r0 * ldC + col)       = make_float2(c0 + b0, c1 + b1);
                *(float2*)(Cf + (size_t)(r0 + 8) * ldC + col) = make_float2(c2 + b0, c3 + b1);
            }
        }
    }
}

// ---------------- launch -------------------------------------------------------------
extern "C" void kernel_launch(void* const* d_in, const int* in_sizes, int n_in,
                              void* d_out, int out_size) {
    const float* x      = (const float*)d_in[0];   // [N, D]
    const float* w_gate = (const float*)d_in[1];   // [D, E]
    const float* w1     = (const float*)d_in[2];   // [E, D, H]
    const float* w2     = (const float*)d_in[3];   // [E, H, D]
    const float* w_proj = (const float*)d_in[4];   // [D, EMB]
    const float* b_proj = (const float*)d_in[5];   // [EMB]
    float* out = (float*)d_out;                    // [N, EMB]

    __half *xh_p, *h_p, *yh_p, *w1t_p, *w2t_p, *wpt_p;
    float *y_p;
    cudaGetSymbolAddress((void**)&xh_p, g_xh);
    cudaGetSymbolAddress((void**)&h_p, g_h);
    cudaGetSymbolAddress((void**)&y_p, g_y);
    cudaGetSymbolAddress((void**)&yh_p, g_yh);
    cudaGetSymbolAddress((void**)&w1t_p, g_w1t);
    cudaGetSymbolAddress((void**)&w2t_p, g_w2t);
    cudaGetSymbolAddress((void**)&wpt_p, g_wpt);

    cudaFuncSetAttribute(gemm_mma<DIM, 0>, cudaFuncAttributeMaxDynamicSharedMemorySize, SMEM_BYTES);
    cudaFuncSetAttribute(gemm_mma<HID, 1>, cudaFuncAttributeMaxDynamicSharedMemorySize, SMEM_BYTES);
    cudaFuncSetAttribute(gemm_mma<DIM, 2>, cudaFuncAttributeMaxDynamicSharedMemorySize, SMEM_BYTES);

    const int MAX_TILES = SLOTS / BM;   // 1028

    // prep + routing
    init_counts_kernel<<<1, 32>>>();
    slot_init_kernel<<<(SLOTS + 255) / 256, 256>>>();
    cudaMemsetAsync(y_p, 0, (size_t)N_TOK * DIM * sizeof(float));
    transpose_half_kernel<<<dim3(HID / 32, DIM / 32, NEXP), dim3(32, 8)>>>(w1, w1t_p, DIM, HID);
    transpose_half_kernel<<<dim3(DIM / 32, HID / 32, NEXP), dim3(32, 8)>>>(w2, w2t_p, HID, DIM);
    transpose_half_kernel<<<dim3(EMBD / 32, DIM / 32, 1), dim3(32, 8)>>>(w_proj, wpt_p, DIM, EMBD);
    gate_assign_kernel<<<N_TOK / 8, 256>>>(x, w_gate, xh_p);
    offsets_kernel<<<1, 32>>>();
    place_kernel<<<N_TOK / 256, 256>>>();

    // GEMM1 sparse: h[slot] = fp16(gate * gelu(x[tok] @ w1[e]))
    gemm_mma<DIM, 0><<<dim3(HID / BN, MAX_TILES), 256, SMEM_BYTES>>>(
        xh_p, w1t_p, h_p, HID, nullptr, HID * DIM);

    // GEMM2 sparse: y[tok] += h[slot] @ w2[e]^T   (fp32 RED, 2 contributions/token)
    gemm_mma<HID, 1><<<dim3(DIM / BN, MAX_TILES), 256, SMEM_BYTES>>>(
        h_p, w2t_p, y_p, DIM, nullptr, DIM * HID);

    // y -> fp16
    tohalf_y_kernel<<<(N_TOK * DIM / 4) / 256, 256>>>((const float4*)y_p, (uint2*)yh_p);

    // proj: out = yh @ w_proj + b
    gemm_mma<DIM, 2><<<dim3(EMBD / BN, N_TOK / BM), 256, SMEM_BYTES>>>(
        yh_p, wpt_p, out, EMBD, b_proj, 0);
}